// round 1
// baseline (speedup 1.0000x reference)
#include <cuda_runtime.h>

#define NUM_SPECIES 7
#define BMOL 1024
#define NA 48
#define NATOMS (BMOL * NA)   /* 49152 */
#define FDIM 384

// ---------------- device scratch (no allocations allowed) ----------------
__device__ int   g_counts[NUM_SPECIES];
__device__ int   g_lists[NUM_SPECIES * NATOMS];
__device__ float g_atom_energy[NATOMS];

// ---------------- bucketize atoms by species ----------------
__global__ void zero_kernel() {
    if (threadIdx.x < NUM_SPECIES) g_counts[threadIdx.x] = 0;
}

__global__ void bucket_kernel(const int* __restrict__ species) {
    int i = blockIdx.x * blockDim.x + threadIdx.x;
    if (i < NATOMS) {
        int s = species[i];
        int pos = atomicAdd(&g_counts[s], 1);
        g_lists[s * NATOMS + pos] = i;
    }
}

// ---------------- CELU(alpha = 0.1) ----------------
__device__ __forceinline__ float celu01(float x) {
    return x > 0.f ? x : 0.1f * (__expf(10.f * x) - 1.f);
}

// smem strides, all == 1 (mod 32) so row index shifts the bank pattern
#define S_IN1 385   /* K=384 input  */
#define S_H1  257   /* 256 hidden   */
#define S_H2  193   /* 192 hidden   */
#define S_H3  161   /* 160 hidden   */
#define BS_LD 33    /* weight tile row stride */

// One fused layer: out[32][N] = celu(in[32][K] * W[N][K]^T + bias)
// 256 threads; register tile = 2 atoms x 4 neurons; weight staging 64x32.
template<int K, int N>
__device__ __forceinline__ void layer(
    const float* __restrict__ W, const float* __restrict__ bias,
    const float* __restrict__ in, int inS,
    float* __restrict__ out, int outS,
    float* __restrict__ Bs, int tid)
{
    const int tn = tid & 15;   // neuron group 0..15
    const int tm = tid >> 4;   // atom group   0..15
    const int m0 = tm * 2;

    for (int nt = 0; nt < N; nt += 64) {
        float acc[2][4];
#pragma unroll
        for (int i = 0; i < 2; i++)
#pragma unroll
            for (int j = 0; j < 4; j++) acc[i][j] = 0.f;

        for (int k0 = 0; k0 < K; k0 += 32) {
            __syncthreads();
            // cooperative load of W tile [64 neurons][32 k], zero-padded
#pragma unroll
            for (int i = 0; i < 8; i++) {
                int idx = tid + i * 256;
                int n  = idx >> 5;
                int kk = idx & 31;
                int gn = nt + n;
                Bs[n * BS_LD + kk] = (gn < N) ? W[gn * K + k0 + kk] : 0.f;
            }
            __syncthreads();
#pragma unroll
            for (int kk = 0; kk < 32; kk++) {
                float a0 = in[m0 * inS + k0 + kk];
                float a1 = in[(m0 + 1) * inS + k0 + kk];
#pragma unroll
                for (int j = 0; j < 4; j++) {
                    float w = Bs[(tn + 16 * j) * BS_LD + kk];
                    acc[0][j] += a0 * w;
                    acc[1][j] += a1 * w;
                }
            }
        }
        // epilogue: bias + CELU, guarded store
#pragma unroll
        for (int i = 0; i < 2; i++)
#pragma unroll
            for (int j = 0; j < 4; j++) {
                int gn = nt + tn + 16 * j;
                if (gn < N)
                    out[(m0 + i) * outS + gn] = celu01(acc[i][j] + bias[gn]);
            }
    }
    __syncthreads();
}

// ---------------- main MLP kernel: one block = (species, 32-atom tile) ----
__global__ void __launch_bounds__(256, 2)
mlp_kernel(const float* __restrict__ aev,
           const float* __restrict__ W1, const float* __restrict__ b1,
           const float* __restrict__ W2, const float* __restrict__ b2,
           const float* __restrict__ W3, const float* __restrict__ b3,
           const float* __restrict__ W4, const float* __restrict__ b4)
{
    const int s     = blockIdx.y;
    const int tile0 = blockIdx.x * 32;
    const int cnt   = g_counts[s];
    if (tile0 >= cnt) return;

    extern __shared__ float smem[];
    float* bufA = smem;                 // 32 * 385
    float* bufB = bufA + 32 * S_IN1;    // 32 * 257
    float* Bs   = bufB + 32 * S_H1;     // 64 * 33
    __shared__ int s_idx[32];

    const int tid = threadIdx.x;
    if (tid < 32) {
        int p = tile0 + tid;
        s_idx[tid] = (p < cnt) ? g_lists[s * NATOMS + p] : -1;
    }
    __syncthreads();

    // gather 32 aev rows into smem (coalesced per row)
    for (int i = tid; i < 32 * FDIM; i += 256) {
        int m = i / FDIM;
        int k = i - m * FDIM;
        int g = s_idx[m];
        bufA[m * S_IN1 + k] = (g >= 0) ? aev[(size_t)g * FDIM + k] : 0.f;
    }
    // layer() begins with __syncthreads(), covering the writes above

    layer<384, 256>(W1 + s * 256 * 384, b1 + s * 256, bufA, S_IN1, bufB, S_H1, Bs, tid);
    layer<256, 192>(W2 + s * 192 * 256, b2 + s * 192, bufB, S_H1,  bufA, S_H2, Bs, tid);
    layer<192, 160>(W3 + s * 160 * 192, b3 + s * 160, bufA, S_H2,  bufB, S_H3, Bs, tid);

    // final layer 160 -> 1 : warp-parallel dot product per atom
    const int warp = tid >> 5, lane = tid & 31;
    const float* w4 = W4 + s * 160;
    const float  b4v = b4[s];
    for (int m = warp; m < 32; m += 8) {
        float sum = 0.f;
#pragma unroll
        for (int k = lane; k < 160; k += 32)
            sum += bufB[m * S_H3 + k] * w4[k];
#pragma unroll
        for (int o = 16; o > 0; o >>= 1)
            sum += __shfl_down_sync(0xffffffffu, sum, o);
        if (lane == 0) {
            int g = s_idx[m];
            if (g >= 0) g_atom_energy[g] = sum + b4v;
        }
    }
}

// ---------------- deterministic per-molecule reduction ----------------
__global__ void reduce_kernel(float* __restrict__ out) {
    __shared__ float sh[64];
    const int b = blockIdx.x;
    const int t = threadIdx.x;
    sh[t] = (t < NA) ? g_atom_energy[b * NA + t] : 0.f;
    __syncthreads();
#pragma unroll
    for (int o = 32; o > 0; o >>= 1) {
        if (t < o) sh[t] += sh[t + o];
        __syncthreads();
    }
    if (t == 0) out[b] = sh[0];
}

// ---------------- launch ----------------
extern "C" void kernel_launch(void* const* d_in, const int* in_sizes, int n_in,
                              void* d_out, int out_size)
{
    const int*   species = (const int*)  d_in[0];
    const float* aev     = (const float*)d_in[1];
    const float* W1      = (const float*)d_in[2];
    const float* b1      = (const float*)d_in[3];
    const float* W2      = (const float*)d_in[4];
    const float* b2      = (const float*)d_in[5];
    const float* W3      = (const float*)d_in[6];
    const float* b3      = (const float*)d_in[7];
    const float* W4      = (const float*)d_in[8];
    const float* b4      = (const float*)d_in[9];
    float* out = (float*)d_out;

    const int smem_bytes = (32 * S_IN1 + 32 * S_H1 + 64 * BS_LD) * (int)sizeof(float); // 90624
    cudaFuncSetAttribute(mlp_kernel, cudaFuncAttributeMaxDynamicSharedMemorySize, smem_bytes);

    zero_kernel<<<1, 32>>>();
    bucket_kernel<<<(NATOMS + 255) / 256, 256>>>(species);

    dim3 grid(NATOMS / 32, NUM_SPECIES);   // worst case: all atoms one species
    mlp_kernel<<<grid, 256, smem_bytes>>>(aev, W1, b1, W2, b2, W3, b3, W4, b4);

    reduce_kernel<<<BMOL, 64>>>(out);
}

// round 3
// speedup vs baseline: 2.4199x; 2.4199x over previous
#include <cuda_runtime.h>
#include <cuda_bf16.h>
#include <cstdint>

#define NUM_SPECIES 7
#define BMOL 1024
#define NA 48
#define NATOMS (BMOL * NA)   /* 49152 */
#define FDIM 384
#define TILE_M 64

/* layer sizes */
#define N1 256
#define N2 192
#define N3 160
#define K1 384
#define K2 256
#define K3 192

/* pre-split weight pool (bf16 hi/lo), concatenated W1|W2|W3 */
#define W1_ELEMS (NUM_SPECIES * N1 * K1)
#define W2_ELEMS (NUM_SPECIES * N2 * K2)
#define W3_ELEMS (NUM_SPECIES * N3 * K3)
#define W_OFF1 0
#define W_OFF2 (W1_ELEMS)
#define W_OFF3 (W1_ELEMS + W2_ELEMS)
#define W_TOTAL (W1_ELEMS + W2_ELEMS + W3_ELEMS)

__device__ int   g_counts[NUM_SPECIES];
__device__ int   g_lists[NUM_SPECIES * NATOMS];
__device__ float g_atom_energy[NATOMS];
__device__ __align__(16) __nv_bfloat16 g_wh[W_TOTAL];
__device__ __align__(16) __nv_bfloat16 g_wl[W_TOTAL];

/* ---------------- SMEM byte offsets ------------------------------------- */
/* R0: 64 rows x 768B (hi, lo)   R1: 64 rows x 512B (hi, lo)                */
#define R0_HI 0
#define R0_LO 49152
#define R1_HI 98304
#define R1_LO 131072
#define WBUF  163840          /* 2 x (8KB hi + 8KB lo) = 32 KB */
#define SIDX  196608          /* 64 x int */
#define SMEM_TOTAL 196992

/* ---------------- PTX helpers ------------------------------------------- */
__device__ __forceinline__ uint32_t smem_u32(const void* p) {
    uint32_t a;
    asm("{ .reg .u64 t; cvta.to.shared.u64 t, %1; cvt.u32.u64 %0, t; }" : "=r"(a) : "l"(p));
    return a;
}
__device__ __forceinline__ void cp16(uint32_t dst, const void* src) {
    asm volatile("cp.async.ca.shared.global [%0], [%1], 16;" :: "r"(dst), "l"(src));
}
#define CP_COMMIT() asm volatile("cp.async.commit_group;" ::: "memory")
#define CP_WAIT1()  asm volatile("cp.async.wait_group 1;" ::: "memory")

__device__ __forceinline__ void ldsm4(uint32_t (&r)[4], uint32_t a) {
    asm volatile("ldmatrix.sync.aligned.m8n8.x4.shared.b16 {%0,%1,%2,%3}, [%4];"
        : "=r"(r[0]), "=r"(r[1]), "=r"(r[2]), "=r"(r[3]) : "r"(a));
}
__device__ __forceinline__ void mma16816(float (&c)[4], const uint32_t (&a)[4],
                                         uint32_t b0, uint32_t b1) {
    asm volatile("mma.sync.aligned.m16n8k16.row.col.f32.bf16.bf16.f32 "
        "{%0,%1,%2,%3},{%4,%5,%6,%7},{%8,%9},{%0,%1,%2,%3};"
        : "+f"(c[0]), "+f"(c[1]), "+f"(c[2]), "+f"(c[3])
        : "r"(a[0]), "r"(a[1]), "r"(a[2]), "r"(a[3]), "r"(b0), "r"(b1));
}

/* swizzled byte offset of (row r, byte-in-row kb); rowb multiple of 128 */
__device__ __forceinline__ uint32_t swoff(uint32_t r, uint32_t kb, uint32_t rowb) {
    return r * rowb + (kb & ~127u) + ((((kb >> 4) ^ r) & 7u) << 4) + (kb & 15u);
}

__device__ __forceinline__ void split2(float a, float b, uint32_t& hp, uint32_t& lp) {
    __nv_bfloat16 ha = __float2bfloat16(a), hb = __float2bfloat16(b);
    __nv_bfloat16 la = __float2bfloat16(a - __bfloat162float(ha));
    __nv_bfloat16 lb = __float2bfloat16(b - __bfloat162float(hb));
    hp = ((uint32_t)__bfloat16_as_ushort(hb) << 16) | __bfloat16_as_ushort(ha);
    lp = ((uint32_t)__bfloat16_as_ushort(lb) << 16) | __bfloat16_as_ushort(la);
}
__device__ __forceinline__ float celu01(float x) {
    return x > 0.f ? x : 0.1f * (__expf(10.f * x) - 1.f);
}

/* ---------------- prep / bucket ----------------------------------------- */
__global__ void prep_split_kernel(const float* __restrict__ W1,
                                  const float* __restrict__ W2,
                                  const float* __restrict__ W3) {
    int i = blockIdx.x * blockDim.x + threadIdx.x;
    if (i >= W_TOTAL) return;
    float v;
    if (i < W_OFF2)      v = W1[i - W_OFF1];
    else if (i < W_OFF3) v = W2[i - W_OFF2];
    else                 v = W3[i - W_OFF3];
    __nv_bfloat16 h = __float2bfloat16(v);
    g_wh[i] = h;
    g_wl[i] = __float2bfloat16(v - __bfloat162float(h));
}
__global__ void zero_kernel() { if (threadIdx.x < NUM_SPECIES) g_counts[threadIdx.x] = 0; }
__global__ void bucket_kernel(const int* __restrict__ species) {
    int i = blockIdx.x * blockDim.x + threadIdx.x;
    if (i < NATOMS) {
        int s = species[i];
        g_lists[s * NATOMS + atomicAdd(&g_counts[s], 1)] = i;
    }
}

/* ---------------- one MLP layer on tensor cores ------------------------- */
/* out[64, N] = celu(in[64, K] * W[N, K]^T + bias); in/out swizzled bf16 hi/lo */
template<int K, int N, int RIN, int ROUT>
__device__ __forceinline__ void mlp_layer(
    char* smem, uint32_t smb,
    uint32_t IN_HI, uint32_t IN_LO, uint32_t OUT_HI, uint32_t OUT_LO,
    const __nv_bfloat16* __restrict__ Wh, const __nv_bfloat16* __restrict__ Wl,
    const float* __restrict__ bias)
{
    const int tid = threadIdx.x;
    const int lane = tid & 31, wid = tid >> 5;
    const int wm = wid & 1, wn = wid >> 1;
    constexpr int NK = K / 64;

    const uint32_t lrow = (uint32_t)((lane & 7) + (lane & 8)); /* 0..15 */
    const uint32_t lkb  = (uint32_t)((lane >> 4) << 4);        /* 0 / 16 */

    for (int n0 = 0; n0 < N; n0 += 64) {
        const int nsz = (N - n0 < 64) ? (N - n0) : 64;   /* 64 or 32 */
        const bool active = (wn * 16) < nsz;

        /* stage weight chunk kcc into buffer buf (hi at +0, lo at +8192) */
        auto stage = [&](int kcc, int buf) {
            uint32_t wb = smb + WBUF + (uint32_t)buf * 16384u;
            for (int it = tid; it < nsz * 8; it += 256) {
                int rr = it >> 3, cc = it & 7;
                size_t gsrc = (size_t)(n0 + rr) * K + kcc * 64 + cc * 8;
                uint32_t d = wb + (uint32_t)(rr * 128 + ((cc ^ (rr & 7)) << 4));
                cp16(d, Wh + gsrc);
                cp16(d + 8192, Wl + gsrc);
            }
        };

        stage(0, 0); CP_COMMIT();
        stage(1, 1); CP_COMMIT();

        float acc[2][2][4];
#pragma unroll
        for (int a = 0; a < 2; a++)
#pragma unroll
            for (int b = 0; b < 2; b++)
#pragma unroll
                for (int c = 0; c < 4; c++) acc[a][b][c] = 0.f;

        for (int kc = 0; kc < NK; kc++) {
            CP_WAIT1();
            __syncthreads();
            const uint32_t wb = smb + WBUF + (uint32_t)(kc & 1) * 16384u;
            if (active) {
#pragma unroll
                for (int k16 = 0; k16 < 4; k16++) {
                    const uint32_t kb = (uint32_t)(kc * 128 + k16 * 32);
                    uint32_t ah[2][4], al[2][4], wh[4], wl[4];
#pragma unroll
                    for (int mt = 0; mt < 2; mt++) {
                        uint32_t r = (uint32_t)(wm * 32 + mt * 16) + lrow;
                        uint32_t a = swoff(r, kb + lkb, RIN);
                        ldsm4(ah[mt], smb + IN_HI + a);
                        ldsm4(al[mt], smb + IN_LO + a);
                    }
                    {
                        uint32_t wrow = (uint32_t)(wn * 16) + lrow;
                        uint32_t wkb  = (uint32_t)(k16 * 32) + lkb;
                        uint32_t wo = wrow * 128 + ((((wkb >> 4) ^ wrow) & 7u) << 4);
                        ldsm4(wh, wb + wo);
                        ldsm4(wl, wb + 8192 + wo);
                    }
#pragma unroll
                    for (int mt = 0; mt < 2; mt++)
#pragma unroll
                        for (int nt = 0; nt < 2; nt++) {
                            mma16816(acc[mt][nt], ah[mt], wh[nt], wh[nt + 2]);
                            mma16816(acc[mt][nt], ah[mt], wl[nt], wl[nt + 2]);
                            mma16816(acc[mt][nt], al[mt], wh[nt], wh[nt + 2]);
                        }
                }
            }
            __syncthreads();
            if (kc + 2 < NK) stage(kc + 2, kc & 1);
            CP_COMMIT();
        }

        /* epilogue: bias + celu + split -> OUT region */
        if (active) {
#pragma unroll
            for (int mt = 0; mt < 2; mt++)
#pragma unroll
                for (int nt = 0; nt < 2; nt++) {
                    uint32_t r0 = (uint32_t)(wm * 32 + mt * 16 + (lane >> 2));
                    int c = n0 + wn * 16 + nt * 8 + 2 * (lane & 3);
                    float b0 = __ldg(bias + c), b1 = __ldg(bias + c + 1);
                    float v00 = celu01(acc[mt][nt][0] + b0);
                    float v01 = celu01(acc[mt][nt][1] + b1);
                    float v10 = celu01(acc[mt][nt][2] + b0);
                    float v11 = celu01(acc[mt][nt][3] + b1);
                    uint32_t hp, lp;
                    uint32_t o0 = swoff(r0, (uint32_t)(2 * c), ROUT);
                    split2(v00, v01, hp, lp);
                    *(uint32_t*)(smem + OUT_HI + o0) = hp;
                    *(uint32_t*)(smem + OUT_LO + o0) = lp;
                    uint32_t o1 = swoff(r0 + 8, (uint32_t)(2 * c), ROUT);
                    split2(v10, v11, hp, lp);
                    *(uint32_t*)(smem + OUT_HI + o1) = hp;
                    *(uint32_t*)(smem + OUT_LO + o1) = lp;
                }
        }
    }
    __syncthreads();
}

/* ---------------- main kernel ------------------------------------------- */
__global__ void __launch_bounds__(256, 1)
mlp_kernel(const float* __restrict__ aev,
           const float* __restrict__ b1, const float* __restrict__ b2,
           const float* __restrict__ b3,
           const float* __restrict__ W4, const float* __restrict__ b4)
{
    const int s = blockIdx.y;
    const int tile0 = blockIdx.x * TILE_M;
    const int cnt = g_counts[s];
    if (tile0 >= cnt) return;

    extern __shared__ char smem[];
    const uint32_t smb = smem_u32(smem);
    const int tid = threadIdx.x;
    int* s_idx = (int*)(smem + SIDX);

    if (tid < TILE_M)
        s_idx[tid] = (tile0 + tid < cnt) ? g_lists[s * NATOMS + tile0 + tid] : -1;
    __syncthreads();

    /* gather + split layer-1 input: 64 rows x 384 f32 -> R0 hi/lo */
    for (int it = tid; it < TILE_M * 96; it += 256) {
        int r = it / 96, q = it - r * 96;
        int g = s_idx[r];
        float4 v = make_float4(0.f, 0.f, 0.f, 0.f);
        if (g >= 0) v = *(const float4*)(aev + (size_t)g * FDIM + q * 4);
        uint32_t h0, l0, h1, l1;
        split2(v.x, v.y, h0, l0);
        split2(v.z, v.w, h1, l1);
        uint32_t o = swoff((uint32_t)r, (uint32_t)(q * 8), 768);
        *(uint2*)(smem + R0_HI + o) = make_uint2(h0, h1);
        *(uint2*)(smem + R0_LO + o) = make_uint2(l0, l1);
    }
    __syncthreads();

    mlp_layer<K1, N1, 768, 512>(smem, smb, R0_HI, R0_LO, R1_HI, R1_LO,
        g_wh + W_OFF1 + (size_t)s * N1 * K1, g_wl + W_OFF1 + (size_t)s * N1 * K1,
        b1 + s * N1);
    mlp_layer<K2, N2, 512, 384>(smem, smb, R1_HI, R1_LO, R0_HI, R0_LO,
        g_wh + W_OFF2 + (size_t)s * N2 * K2, g_wl + W_OFF2 + (size_t)s * N2 * K2,
        b2 + s * N2);
    mlp_layer<K3, N3, 384, 384>(smem, smb, R0_HI, R0_LO, R1_HI, R1_LO,
        g_wh + W_OFF3 + (size_t)s * N3 * K3, g_wl + W_OFF3 + (size_t)s * N3 * K3,
        b3 + s * N3);

    /* layer 4: 160 -> 1 dot product, no activation */
    {
        const int wid = tid >> 5, lane = tid & 31;
        const float* w4s = W4 + s * N3;
        const float  b4v = __ldg(b4 + s);
#pragma unroll
        for (int rr = 0; rr < 8; rr++) {
            int row = wid * 8 + rr;
            float sum = 0.f;
#pragma unroll
            for (int c = lane; c < N3; c += 32) {
                uint32_t o = swoff((uint32_t)row, (uint32_t)(2 * c), 384);
                float hi = __bfloat162float(*(const __nv_bfloat16*)(smem + R1_HI + o));
                float lo = __bfloat162float(*(const __nv_bfloat16*)(smem + R1_LO + o));
                sum += (hi + lo) * __ldg(w4s + c);
            }
#pragma unroll
            for (int o = 16; o > 0; o >>= 1)
                sum += __shfl_down_sync(0xffffffffu, sum, o);
            if (lane == 0) {
                int g = s_idx[row];
                if (g >= 0) g_atom_energy[g] = sum + b4v;
            }
        }
    }
}

/* ---------------- per-molecule reduction -------------------------------- */
__global__ void reduce_kernel(float* __restrict__ out) {
    __shared__ float sh[64];
    const int b = blockIdx.x, t = threadIdx.x;
    sh[t] = (t < NA) ? g_atom_energy[b * NA + t] : 0.f;
    __syncthreads();
#pragma unroll
    for (int o = 32; o > 0; o >>= 1) {
        if (t < o) sh[t] += sh[t + o];
        __syncthreads();
    }
    if (t == 0) out[b] = sh[0];
}

/* ---------------- launch ------------------------------------------------ */
extern "C" void kernel_launch(void* const* d_in, const int* in_sizes, int n_in,
                              void* d_out, int out_size)
{
    const int*   species = (const int*)  d_in[0];
    const float* aev     = (const float*)d_in[1];
    const float* W1      = (const float*)d_in[2];
    const float* b1      = (const float*)d_in[3];
    const float* W2      = (const float*)d_in[4];
    const float* b2      = (const float*)d_in[5];
    const float* W3      = (const float*)d_in[6];
    const float* b3      = (const float*)d_in[7];
    const float* W4      = (const float*)d_in[8];
    const float* b4      = (const float*)d_in[9];
    float* out = (float*)d_out;

    cudaFuncSetAttribute(mlp_kernel, cudaFuncAttributeMaxDynamicSharedMemorySize, SMEM_TOTAL);

    prep_split_kernel<<<(W_TOTAL + 255) / 256, 256>>>(W1, W2, W3);
    zero_kernel<<<1, 32>>>();
    bucket_kernel<<<(NATOMS + 255) / 256, 256>>>(species);

    dim3 grid(NATOMS / TILE_M, NUM_SPECIES);
    mlp_kernel<<<grid, 256, SMEM_TOTAL>>>(aev, b1, b2, b3, W4, b4);

    reduce_kernel<<<BMOL, 64>>>(out);
}

// round 4
// speedup vs baseline: 2.7123x; 1.1208x over previous
#include <cuda_runtime.h>
#include <cuda_bf16.h>
#include <cstdint>

#define NUM_SPECIES 7
#define BMOL 1024
#define NA 48
#define NATOMS (BMOL * NA)   /* 49152 */
#define FDIM 384
#define TILE_M 64
#define NTHREADS 512

/* layer sizes */
#define N1 256
#define N2 192
#define N3 160
#define K1 384
#define K2 256
#define K3 192

/* pre-split weight pool (bf16 hi/lo), concatenated W1|W2|W3 */
#define W1_ELEMS (NUM_SPECIES * N1 * K1)
#define W2_ELEMS (NUM_SPECIES * N2 * K2)
#define W3_ELEMS (NUM_SPECIES * N3 * K3)
#define W_OFF1 0
#define W_OFF2 (W1_ELEMS)
#define W_OFF3 (W1_ELEMS + W2_ELEMS)
#define W_TOTAL (W1_ELEMS + W2_ELEMS + W3_ELEMS)

__device__ int   g_counts[NUM_SPECIES];
__device__ int   g_lists[NUM_SPECIES * NATOMS];
__device__ float g_atom_energy[NATOMS];
__device__ __align__(16) __nv_bfloat16 g_wh[W_TOTAL];
__device__ __align__(16) __nv_bfloat16 g_wl[W_TOTAL];

/* ---------------- SMEM byte offsets ------------------------------------- */
#define R0_HI 0
#define R0_LO 49152
#define R1_HI 98304
#define R1_LO 131072
#define WBUF  163840          /* 2 x (8KB hi + 8KB lo) = 32 KB */
#define SIDX  196608          /* 64 x int */
#define SMEM_TOTAL 196992

/* ---------------- PTX helpers ------------------------------------------- */
__device__ __forceinline__ uint32_t smem_u32(const void* p) {
    uint32_t a;
    asm("{ .reg .u64 t; cvta.to.shared.u64 t, %1; cvt.u32.u64 %0, t; }" : "=r"(a) : "l"(p));
    return a;
}
__device__ __forceinline__ void cp16(uint32_t dst, const void* src) {
    asm volatile("cp.async.ca.shared.global [%0], [%1], 16;" :: "r"(dst), "l"(src));
}
#define CP_COMMIT() asm volatile("cp.async.commit_group;" ::: "memory")
#define CP_WAIT1()  asm volatile("cp.async.wait_group 1;" ::: "memory")

__device__ __forceinline__ void ldsm4(uint32_t (&r)[4], uint32_t a) {
    asm volatile("ldmatrix.sync.aligned.m8n8.x4.shared.b16 {%0,%1,%2,%3}, [%4];"
        : "=r"(r[0]), "=r"(r[1]), "=r"(r[2]), "=r"(r[3]) : "r"(a));
}
__device__ __forceinline__ void mma16816(float (&c)[4], const uint32_t (&a)[4],
                                         uint32_t b0, uint32_t b1) {
    asm volatile("mma.sync.aligned.m16n8k16.row.col.f32.bf16.bf16.f32 "
        "{%0,%1,%2,%3},{%4,%5,%6,%7},{%8,%9},{%0,%1,%2,%3};"
        : "+f"(c[0]), "+f"(c[1]), "+f"(c[2]), "+f"(c[3])
        : "r"(a[0]), "r"(a[1]), "r"(a[2]), "r"(a[3]), "r"(b0), "r"(b1));
}

/* swizzled byte offset of (row r, byte-in-row kb); rowb multiple of 128 */
__device__ __forceinline__ uint32_t swoff(uint32_t r, uint32_t kb, uint32_t rowb) {
    return r * rowb + (kb & ~127u) + ((((kb >> 4) ^ r) & 7u) << 4) + (kb & 15u);
}

__device__ __forceinline__ void split2(float a, float b, uint32_t& hp, uint32_t& lp) {
    __nv_bfloat16 ha = __float2bfloat16(a), hb = __float2bfloat16(b);
    __nv_bfloat16 la = __float2bfloat16(a - __bfloat162float(ha));
    __nv_bfloat16 lb = __float2bfloat16(b - __bfloat162float(hb));
    hp = ((uint32_t)__bfloat16_as_ushort(hb) << 16) | __bfloat16_as_ushort(ha);
    lp = ((uint32_t)__bfloat16_as_ushort(lb) << 16) | __bfloat16_as_ushort(la);
}
__device__ __forceinline__ float celu01(float x) {
    return x > 0.f ? x : 0.1f * (__expf(10.f * x) - 1.f);
}

/* ---------------- prep / bucket ----------------------------------------- */
__global__ void prep_split_kernel(const float* __restrict__ W1,
                                  const float* __restrict__ W2,
                                  const float* __restrict__ W3) {
    int i = blockIdx.x * blockDim.x + threadIdx.x;
    if (i >= W_TOTAL) return;
    float v;
    if (i < W_OFF2)      v = W1[i - W_OFF1];
    else if (i < W_OFF3) v = W2[i - W_OFF2];
    else                 v = W3[i - W_OFF3];
    __nv_bfloat16 h = __float2bfloat16(v);
    g_wh[i] = h;
    g_wl[i] = __float2bfloat16(v - __bfloat162float(h));
}
__global__ void zero_kernel() { if (threadIdx.x < NUM_SPECIES) g_counts[threadIdx.x] = 0; }
__global__ void bucket_kernel(const int* __restrict__ species) {
    int i = blockIdx.x * blockDim.x + threadIdx.x;
    if (i < NATOMS) {
        int s = species[i];
        g_lists[s * NATOMS + atomicAdd(&g_counts[s], 1)] = i;
    }
}

/* ---------------- one MLP layer on tensor cores ------------------------- */
/* out[64, N] = celu(in[64, K] * W[N, K]^T + bias); warp grid 4(M) x 4(N)   */
template<int K, int N, int RIN, int ROUT>
__device__ __forceinline__ void mlp_layer(
    char* smem, uint32_t smb,
    uint32_t IN_HI, uint32_t IN_LO, uint32_t OUT_HI, uint32_t OUT_LO,
    const __nv_bfloat16* __restrict__ Wh, const __nv_bfloat16* __restrict__ Wl,
    const float* __restrict__ bias)
{
    const int tid = threadIdx.x;
    const int lane = tid & 31, wid = tid >> 5;
    const int wm = wid & 3, wn = wid >> 2;       /* 4 x 4 warps */
    constexpr int NK = K / 64;

    const uint32_t lrow = (uint32_t)((lane & 7) + (lane & 8)); /* 0..15 */
    const uint32_t lkb  = (uint32_t)((lane >> 4) << 4);        /* 0 / 16 */
    const uint32_t arow = (uint32_t)(wm * 16) + lrow;
    const uint32_t wrow = (uint32_t)(wn * 16) + lrow;

    for (int n0 = 0; n0 < N; n0 += 64) {
        const int nsz = (N - n0 < 64) ? (N - n0) : 64;   /* 64 or 32 */
        const bool active = (wn * 16) < nsz;

        /* stage weight chunk kcc into buffer buf (hi at +0, lo at +8192) */
        auto stage = [&](int kcc, int buf) {
            uint32_t wb = smb + WBUF + (uint32_t)buf * 16384u;
            for (int it = tid; it < nsz * 8; it += NTHREADS) {
                int rr = it >> 3, cc = it & 7;
                size_t gsrc = (size_t)(n0 + rr) * K + kcc * 64 + cc * 8;
                uint32_t d = wb + (uint32_t)(rr * 128 + ((cc ^ (rr & 7)) << 4));
                cp16(d, Wh + gsrc);
                cp16(d + 8192, Wl + gsrc);
            }
        };

        stage(0, 0); CP_COMMIT();
        stage(1, 1); CP_COMMIT();

        float acc[2][4];
#pragma unroll
        for (int b = 0; b < 2; b++)
#pragma unroll
            for (int c = 0; c < 4; c++) acc[b][c] = 0.f;

        for (int kc = 0; kc < NK; kc++) {
            CP_WAIT1();
            __syncthreads();
            const uint32_t wb = smb + WBUF + (uint32_t)(kc & 1) * 16384u;
            if (active) {
                /* ping-pong fragment prefetch across the 4 k16 steps */
                uint32_t ah[2][4], al[2][4], wh[2][4], wl[2][4];
                auto frag_load = [&](int k16, int slot) {
                    const uint32_t kb = (uint32_t)(kc * 128 + k16 * 32);
                    uint32_t a = swoff(arow, kb + lkb, RIN);
                    ldsm4(ah[slot], smb + IN_HI + a);
                    ldsm4(al[slot], smb + IN_LO + a);
                    uint32_t wkb = (uint32_t)(k16 * 32) + lkb;
                    uint32_t wo = wrow * 128 + ((((wkb >> 4) ^ wrow) & 7u) << 4);
                    ldsm4(wh[slot], wb + wo);
                    ldsm4(wl[slot], wb + 8192 + wo);
                };
                frag_load(0, 0);
#pragma unroll
                for (int k16 = 0; k16 < 4; k16++) {
                    const int cur = k16 & 1;
                    if (k16 < 3) frag_load(k16 + 1, cur ^ 1);
#pragma unroll
                    for (int nt = 0; nt < 2; nt++) {
                        mma16816(acc[nt], ah[cur], wh[cur][nt], wh[cur][nt + 2]);
                        mma16816(acc[nt], ah[cur], wl[cur][nt], wl[cur][nt + 2]);
                        mma16816(acc[nt], al[cur], wh[cur][nt], wh[cur][nt + 2]);
                    }
                }
            }
            __syncthreads();
            if (kc + 2 < NK) stage(kc + 2, kc & 1);
            CP_COMMIT();
        }

        /* epilogue: bias + celu + split -> OUT region */
        if (active) {
#pragma unroll
            for (int nt = 0; nt < 2; nt++) {
                uint32_t r0 = (uint32_t)(wm * 16 + (lane >> 2));
                int c = n0 + wn * 16 + nt * 8 + 2 * (lane & 3);
                float b0 = __ldg(bias + c), b1 = __ldg(bias + c + 1);
                float v00 = celu01(acc[nt][0] + b0);
                float v01 = celu01(acc[nt][1] + b1);
                float v10 = celu01(acc[nt][2] + b0);
                float v11 = celu01(acc[nt][3] + b1);
                uint32_t hp, lp;
                uint32_t o0 = swoff(r0, (uint32_t)(2 * c), ROUT);
                split2(v00, v01, hp, lp);
                *(uint32_t*)(smem + OUT_HI + o0) = hp;
                *(uint32_t*)(smem + OUT_LO + o0) = lp;
                uint32_t o1 = swoff(r0 + 8, (uint32_t)(2 * c), ROUT);
                split2(v10, v11, hp, lp);
                *(uint32_t*)(smem + OUT_HI + o1) = hp;
                *(uint32_t*)(smem + OUT_LO + o1) = lp;
            }
        }
    }
    __syncthreads();
}

/* ---------------- main kernel ------------------------------------------- */
__global__ void __launch_bounds__(NTHREADS, 1)
mlp_kernel(const float* __restrict__ aev,
           const float* __restrict__ b1, const float* __restrict__ b2,
           const float* __restrict__ b3,
           const float* __restrict__ W4, const float* __restrict__ b4)
{
    const int s = blockIdx.y;
    const int tile0 = blockIdx.x * TILE_M;
    const int cnt = g_counts[s];
    if (tile0 >= cnt) return;

    extern __shared__ char smem[];
    const uint32_t smb = smem_u32(smem);
    const int tid = threadIdx.x;
    int* s_idx = (int*)(smem + SIDX);

    if (tid < TILE_M)
        s_idx[tid] = (tile0 + tid < cnt) ? g_lists[s * NATOMS + tile0 + tid] : -1;
    __syncthreads();

    /* gather + split layer-1 input: 64 rows x 384 f32 -> R0 hi/lo */
    for (int it = tid; it < TILE_M * 96; it += NTHREADS) {
        int r = it / 96, q = it - r * 96;
        int g = s_idx[r];
        float4 v = make_float4(0.f, 0.f, 0.f, 0.f);
        if (g >= 0) v = *(const float4*)(aev + (size_t)g * FDIM + q * 4);
        uint32_t h0, l0, h1, l1;
        split2(v.x, v.y, h0, l0);
        split2(v.z, v.w, h1, l1);
        uint32_t o = swoff((uint32_t)r, (uint32_t)(q * 8), 768);
        *(uint2*)(smem + R0_HI + o) = make_uint2(h0, h1);
        *(uint2*)(smem + R0_LO + o) = make_uint2(l0, l1);
    }
    __syncthreads();

    mlp_layer<K1, N1, 768, 512>(smem, smb, R0_HI, R0_LO, R1_HI, R1_LO,
        g_wh + W_OFF1 + (size_t)s * N1 * K1, g_wl + W_OFF1 + (size_t)s * N1 * K1,
        b1 + s * N1);
    mlp_layer<K2, N2, 512, 384>(smem, smb, R1_HI, R1_LO, R0_HI, R0_LO,
        g_wh + W_OFF2 + (size_t)s * N2 * K2, g_wl + W_OFF2 + (size_t)s * N2 * K2,
        b2 + s * N2);
    mlp_layer<K3, N3, 384, 384>(smem, smb, R0_HI, R0_LO, R1_HI, R1_LO,
        g_wh + W_OFF3 + (size_t)s * N3 * K3, g_wl + W_OFF3 + (size_t)s * N3 * K3,
        b3 + s * N3);

    /* layer 4: 160 -> 1 dot product, no activation */
    {
        const int wid = tid >> 5, lane = tid & 31;
        const float* w4s = W4 + s * N3;
        const float  b4v = __ldg(b4 + s);
#pragma unroll
        for (int rr = 0; rr < 4; rr++) {
            int row = wid * 4 + rr;
            float sum = 0.f;
#pragma unroll
            for (int c = lane; c < N3; c += 32) {
                uint32_t o = swoff((uint32_t)row, (uint32_t)(2 * c), 384);
                float hi = __bfloat162float(*(const __nv_bfloat16*)(smem + R1_HI + o));
                float lo = __bfloat162float(*(const __nv_bfloat16*)(smem + R1_LO + o));
                sum += (hi + lo) * __ldg(w4s + c);
            }
#pragma unroll
            for (int o = 16; o > 0; o >>= 1)
                sum += __shfl_down_sync(0xffffffffu, sum, o);
            if (lane == 0) {
                int g = s_idx[row];
                if (g >= 0) g_atom_energy[g] = sum + b4v;
            }
        }
    }
}

/* ---------------- per-molecule reduction -------------------------------- */
__global__ void reduce_kernel(float* __restrict__ out) {
    __shared__ float sh[64];
    const int b = blockIdx.x, t = threadIdx.x;
    sh[t] = (t < NA) ? g_atom_energy[b * NA + t] : 0.f;
    __syncthreads();
#pragma unroll
    for (int o = 32; o > 0; o >>= 1) {
        if (t < o) sh[t] += sh[t + o];
        __syncthreads();
    }
    if (t == 0) out[b] = sh[0];
}

/* ---------------- launch ------------------------------------------------ */
extern "C" void kernel_launch(void* const* d_in, const int* in_sizes, int n_in,
                              void* d_out, int out_size)
{
    const int*   species = (const int*)  d_in[0];
    const float* aev     = (const float*)d_in[1];
    const float* W1      = (const float*)d_in[2];
    const float* b1      = (const float*)d_in[3];
    const float* W2      = (const float*)d_in[4];
    const float* b2      = (const float*)d_in[5];
    const float* W3      = (const float*)d_in[6];
    const float* b3      = (const float*)d_in[7];
    const float* W4      = (const float*)d_in[8];
    const float* b4      = (const float*)d_in[9];
    float* out = (float*)d_out;

    cudaFuncSetAttribute(mlp_kernel, cudaFuncAttributeMaxDynamicSharedMemorySize, SMEM_TOTAL);

    prep_split_kernel<<<(W_TOTAL + 255) / 256, 256>>>(W1, W2, W3);
    zero_kernel<<<1, 32>>>();
    bucket_kernel<<<(NATOMS + 255) / 256, 256>>>(species);

    dim3 grid(NATOMS / TILE_M, NUM_SPECIES);
    mlp_kernel<<<grid, NTHREADS, SMEM_TOTAL>>>(aev, b1, b2, b3, W4, b4);

    reduce_kernel<<<BMOL, 64>>>(out);
}